// round 1
// baseline (speedup 1.0000x reference)
#include <cuda_runtime.h>
#include <math.h>

#define BB 2
#define NN 4096
#define DD 64
#define HH 256
#define KK 16
#define NPTS (BB*NN)
#define GRID3 148

// ---------------- scratch (static device allocations; no cudaMalloc) -------
__device__ float g_qkv[NPTS*192];      // q|k|v per point
__device__ int   g_idx[NPTS*KK];       // knn indices
__device__ float g_y[NPTS*DD];         // pre-BN output of fc
__device__ float g_part[GRID3*2*DD];   // per-block partial sum / sumsq
__device__ float g_mv[2*DD];           // mean, rstd

// ---------------- kernel 1: QKV GEMM  (8192x64 @ 64x192) -------------------
__global__ void qkv_kernel(const float* __restrict__ x,
                           const float* __restrict__ w,
                           const float* __restrict__ bq) {
    extern __shared__ float sm[];
    float* ws = sm;             // 64*192
    float* xs = sm + 64*192;    // 64*64
    int tid = threadIdx.x;      // 192 threads
    for (int i = tid; i < 64*192; i += 192) ws[i] = w[i];
    int row0 = blockIdx.x * 64;
    for (int i = tid; i < 64*64; i += 192) xs[i] = x[row0*64 + i];
    __syncthreads();
    float bb = bq[tid];
    for (int r0 = 0; r0 < 64; r0 += 8) {
        float acc[8];
#pragma unroll
        for (int r = 0; r < 8; r++) acc[r] = bb;
        for (int i = 0; i < 64; i++) {
            float wv = ws[i*192 + tid];
#pragma unroll
            for (int r = 0; r < 8; r++) acc[r] = fmaf(xs[(r0+r)*64 + i], wv, acc[r]);
        }
#pragma unroll
        for (int r = 0; r < 8; r++) g_qkv[(row0 + r0 + r)*192 + tid] = acc[r];
    }
}

// ---------------- kernel 2: exact KNN (top-16 smallest (dist, idx)) --------
__device__ __forceinline__ bool lexless(float d1, int i1, float d2, int i2) {
    return (d1 < d2) || (d1 == d2 && i1 < i2);
}

__global__ void knn_kernel(const float* __restrict__ pos) {
    extern __shared__ float sm[];
    float* posX = sm;                 // NN
    float* posY = posX + NN;          // NN
    float* posZ = posY + NN;          // NN
    float* md   = posZ + NN;          // 8*512
    int*   mi   = (int*)(md + 8*512); // 8*512
    int tid = threadIdx.x;
    int warp = tid >> 5, lane = tid & 31;
    int b = blockIdx.x / (NN/8);
    int n = (blockIdx.x % (NN/8))*8 + warp;
    const float* posB = pos + (size_t)b*NN*3;
    for (int i = tid; i < NN; i += 256) {
        posX[i] = posB[i*3+0];
        posY[i] = posB[i*3+1];
        posZ[i] = posB[i*3+2];
    }
    __syncthreads();
    float px = posX[n], py = posY[n], pz = posZ[n];

    float bd[16]; int bi[16];
#pragma unroll
    for (int j = 0; j < 16; j++) { bd[j] = 3.0e38f; bi[j] = 0x7fff0000 + j; }
    float wd = 3.0e38f; int wi = 0x7fff000F;

    for (int c = lane; c < NN; c += 32) {
        float dx = px - posX[c];
        float dy = py - posY[c];
        float dz = pz - posZ[c];
        // match JAX reduction order exactly: (dx*dx + dy*dy) + dz*dz, no fma
        float d2 = __fadd_rn(__fadd_rn(__fmul_rn(dx,dx), __fmul_rn(dy,dy)),
                             __fmul_rn(dz,dz));
        // relaxed squared prefilter (avoids sqrt in the hot path, safe margin)
        float thr2 = __fmul_rn(__fmul_rn(wd, wd), 1.0000005f);
        if (d2 <= thr2) {
            float d = sqrtf(d2);   // exactly what the reference compares on
            if (lexless(d, c, wd, wi)) {
#pragma unroll
                for (int j = 0; j < 16; j++)
                    if (bd[j] == wd && bi[j] == wi) { bd[j] = d; bi[j] = c; }
                wd = bd[0]; wi = bi[0];
#pragma unroll
                for (int j = 1; j < 16; j++)
                    if (lexless(wd, wi, bd[j], bi[j])) { wd = bd[j]; wi = bi[j]; }
            }
        }
    }
    // dump per-lane lists (j-major so lanes are consecutive -> conflict-free)
    float* mdw = md + warp*512;
    int*   miw = mi + warp*512;
#pragma unroll
    for (int j = 0; j < 16; j++) { mdw[j*32 + lane] = bd[j]; miw[j*32 + lane] = bi[j]; }
    __syncwarp();
    int outbase = (b*NN + n)*KK;
    for (int r = 0; r < 16; r++) {
        float cd = 3.0e38f; int ci = 0x7fffffff; int cpos = 0;
#pragma unroll
        for (int j = 0; j < 16; j++) {
            float dv = mdw[j*32 + lane]; int iv = miw[j*32 + lane];
            if (lexless(dv, iv, cd, ci)) { cd = dv; ci = iv; cpos = j*32 + lane; }
        }
#pragma unroll
        for (int off = 16; off > 0; off >>= 1) {
            float od = __shfl_down_sync(0xffffffffu, cd, off);
            int   oi = __shfl_down_sync(0xffffffffu, ci, off);
            int   op = __shfl_down_sync(0xffffffffu, cpos, off);
            if (lexless(od, oi, cd, ci)) { cd = od; ci = oi; cpos = op; }
        }
        if (lane == 0) { g_idx[outbase + r] = ci; mdw[cpos] = 3.0e38f; }
        __syncwarp();
    }
}

// ---------------- kernel 3: fused gather + MLPs + softmax + fc -------------
__global__ __launch_bounds__(256, 1)
void attn_kernel(const float* __restrict__ pos,
                 const float* __restrict__ w_p1, const float* __restrict__ b_p1,
                 const float* __restrict__ w_p2, const float* __restrict__ b_p2,
                 const float* __restrict__ w_a1, const float* __restrict__ b_a1,
                 const float* __restrict__ w_a2, const float* __restrict__ b_a2,
                 const float* __restrict__ w_fc, const float* __restrict__ b_fc) {
    extern __shared__ float sm[];
    float* w_a1s = sm;                // 16384  [d][j]
    float* w_a2s = w_a1s + 16384;     // 16384  [j][d]
    float* w_p2s = w_a2s + 16384;     // 4096   [p][d]
    float* w_fcs = w_p2s + 4096;      // 4096   [c][d]
    float* w_p1s = w_fcs + 4096;      // 192    [c][p]
    float* b_p1s = w_p1s + 192;       // 64
    float* b_p2s = b_p1s + 64;        // 64
    float* b_a1s = b_p2s + 64;        // 256
    float* b_a2s = b_a1s + 256;       // 64
    float* b_fcs = b_a2s + 64;        // 64
    float* qs    = b_fcs + 64;        // 64
    float* rel   = qs + 64;           // 48
    float* p0s   = rel + 48;          // 4
    float* psum  = p0s + 4;           // 64
    float* psum2 = psum + 64;         // 64
    float* hT    = psum2 + 64;        // 1024   [d*16 + k]
    float* t1T   = hT + 1024;         // 1024   [p*16 + k]
    float* vv    = t1T + 1024;        // 1024   [k*64 + d]
    float* scs   = vv + 1024;         // 1024   [k*64 + d]
    float* aggs  = scs + 1024;        // 64
    float* s1    = aggs + 64;         // 4096   [k*256 + j]
    int*   sidx  = (int*)(s1 + 4096); // 16

    int tid = threadIdx.x;
    for (int i = tid; i < 16384; i += 256) w_a1s[i] = w_a1[i];
    for (int i = tid; i < 16384; i += 256) w_a2s[i] = w_a2[i];
    for (int i = tid; i < 4096;  i += 256) w_p2s[i] = w_p2[i];
    for (int i = tid; i < 4096;  i += 256) w_fcs[i] = w_fc[i];
    if (tid < 192) w_p1s[tid] = w_p1[tid];
    b_a1s[tid] = b_a1[tid];
    if (tid < 64) {
        b_p1s[tid] = b_p1[tid]; b_p2s[tid] = b_p2[tid];
        b_a2s[tid] = b_a2[tid]; b_fcs[tid] = b_fc[tid];
        psum[tid] = 0.0f; psum2[tid] = 0.0f;
    }
    __syncthreads();

    for (int p = blockIdx.x; p < NPTS; p += gridDim.x) {
        int b = p >> 12;
        int base = b * NN;
        if (tid < 16) sidx[tid] = g_idx[p*KK + tid];
        if (tid >= 32 && tid < 96) qs[tid-32] = g_qkv[p*192 + (tid-32)];
        if (tid >= 96 && tid < 99) p0s[tid-96] = pos[(size_t)p*3 + (tid-96)];
        __syncthreads();

        // gather: hT = q - k_nb (transposed), vv = v_nb
#pragma unroll
        for (int e = 0; e < 4; e++) {
            int i = tid + e*256;
            int k = i >> 6, d = i & 63;
            int row = (base + sidx[k])*192;
            hT[d*16 + k] = qs[d] - g_qkv[row + 64 + d];
            vv[k*64 + d] = g_qkv[row + 128 + d];
        }
        if (tid < 48) {
            int k = tid / 3, c = tid - k*3;
            rel[k*3 + c] = p0s[c] - pos[(size_t)(base + sidx[k])*3 + c];
        }
        __syncthreads();

        // pos-MLP hidden: t1 = relu(rel @ w_p1 + b_p1), stored transposed
#pragma unroll
        for (int e = 0; e < 4; e++) {
            int i = tid + e*256;
            int k = i >> 6, pp = i & 63;
            float a = b_p1s[pp];
            a = fmaf(rel[k*3+0], w_p1s[0*64 + pp], a);
            a = fmaf(rel[k*3+1], w_p1s[1*64 + pp], a);
            a = fmaf(rel[k*3+2], w_p1s[2*64 + pp], a);
            t1T[pp*16 + k] = fmaxf(a, 0.0f);
        }
        __syncthreads();

        // h += t1 @ w_p2 + b_p2   (2k x 2d register tiles)
        {
            int kt = tid & 7, dt = tid >> 3;     // dt-major keeps hT banks spread
            int k0 = kt*2, d0 = dt*2;
            float a00=0.f, a01=0.f, a10=0.f, a11=0.f;
            for (int q_ = 0; q_ < 64; q_++) {
                float2 t = *(const float2*)&t1T[q_*16 + k0];
                float2 w = *(const float2*)&w_p2s[q_*64 + d0];
                a00 = fmaf(t.x, w.x, a00); a01 = fmaf(t.x, w.y, a01);
                a10 = fmaf(t.y, w.x, a10); a11 = fmaf(t.y, w.y, a11);
            }
            hT[d0*16 + k0]       += a00 + b_p2s[d0];
            hT[(d0+1)*16 + k0]   += a01 + b_p2s[d0+1];
            hT[d0*16 + k0+1]     += a10 + b_p2s[d0];
            hT[(d0+1)*16 + k0+1] += a11 + b_p2s[d0+1];
        }
        __syncthreads();

        // s1 = relu(h @ w_a1 + b_a1)   [16,256], 4k x 4j register tiles
        {
            int kt = tid >> 6, jt = tid & 63;
            int k0 = kt*4, j0 = jt*4;
            float acc[16];
#pragma unroll
            for (int z = 0; z < 16; z++) acc[z] = 0.0f;
            for (int d = 0; d < 64; d++) {
                float4 h = *(const float4*)&hT[d*16 + k0];
                float4 w = *(const float4*)&w_a1s[d*256 + j0];
                acc[0]  = fmaf(h.x, w.x, acc[0]);  acc[1]  = fmaf(h.y, w.x, acc[1]);
                acc[2]  = fmaf(h.z, w.x, acc[2]);  acc[3]  = fmaf(h.w, w.x, acc[3]);
                acc[4]  = fmaf(h.x, w.y, acc[4]);  acc[5]  = fmaf(h.y, w.y, acc[5]);
                acc[6]  = fmaf(h.z, w.y, acc[6]);  acc[7]  = fmaf(h.w, w.y, acc[7]);
                acc[8]  = fmaf(h.x, w.z, acc[8]);  acc[9]  = fmaf(h.y, w.z, acc[9]);
                acc[10] = fmaf(h.z, w.z, acc[10]); acc[11] = fmaf(h.w, w.z, acc[11]);
                acc[12] = fmaf(h.x, w.w, acc[12]); acc[13] = fmaf(h.y, w.w, acc[13]);
                acc[14] = fmaf(h.z, w.w, acc[14]); acc[15] = fmaf(h.w, w.w, acc[15]);
            }
#pragma unroll
            for (int jj = 0; jj < 4; jj++) {
                float bj = b_a1s[j0 + jj];
#pragma unroll
                for (int kk = 0; kk < 4; kk++)
                    s1[(k0+kk)*256 + j0 + jj] = fmaxf(acc[jj*4 + kk] + bj, 0.0f);
            }
        }
        __syncthreads();

        // scores = s1 @ w_a2 + b_a2   [16,64], 2k x 2d tiles
        {
            int kt = tid >> 5, dt = tid & 31;
            int k0 = kt*2, d0 = dt*2;
            float a00=0.f, a01=0.f, a10=0.f, a11=0.f;
            for (int j = 0; j < 256; j++) {
                float sa = s1[k0*256 + j];
                float sb = s1[(k0+1)*256 + j];
                float2 w = *(const float2*)&w_a2s[j*64 + d0];
                a00 = fmaf(sa, w.x, a00); a01 = fmaf(sa, w.y, a01);
                a10 = fmaf(sb, w.x, a10); a11 = fmaf(sb, w.y, a11);
            }
            scs[k0*64 + d0]       = a00 + b_a2s[d0];
            scs[k0*64 + d0+1]     = a01 + b_a2s[d0+1];
            scs[(k0+1)*64 + d0]   = a10 + b_a2s[d0];
            scs[(k0+1)*64 + d0+1] = a11 + b_a2s[d0+1];
        }
        __syncthreads();

        // softmax over K per channel + weighted sum of v
        if (tid < 64) {
            int d = tid;
            float mx = -3.0e38f;
#pragma unroll
            for (int k = 0; k < 16; k++) mx = fmaxf(mx, scs[k*64 + d]);
            float s = 0.0f, a = 0.0f;
#pragma unroll
            for (int k = 0; k < 16; k++) {
                float e = expf(scs[k*64 + d] - mx);
                s += e;
                a = fmaf(e, vv[k*64 + d], a);
            }
            aggs[d] = a / s;
        }
        __syncthreads();

        // fc + per-channel partial batch stats
        if (tid < 64) {
            int d = tid;
            float y = b_fcs[d];
            for (int c = 0; c < 64; c++) y = fmaf(aggs[c], w_fcs[c*64 + d], y);
            g_y[p*64 + d] = y;
            psum[d]  += y;
            psum2[d]  = fmaf(y, y, psum2[d]);
        }
        __syncthreads();
    }
    if (tid < 64) {
        g_part[blockIdx.x*128 + tid]      = psum[tid];
        g_part[blockIdx.x*128 + 64 + tid] = psum2[tid];
    }
}

// ---------------- kernel 4: finish BN statistics ----------------------------
__global__ void bnstats_kernel() {
    int d = threadIdx.x;   // 64 threads
    float s = 0.0f, s2 = 0.0f;
    for (int blk = 0; blk < GRID3; blk++) {
        s  += g_part[blk*128 + d];
        s2 += g_part[blk*128 + 64 + d];
    }
    float mean = s / (float)NPTS;
    float var  = s2 / (float)NPTS - mean*mean;
    g_mv[d]      = mean;
    g_mv[64 + d] = rsqrtf(var + 1e-5f);
}

// ---------------- kernel 5: BN apply + relu + residual ----------------------
__global__ void final_kernel(const float* __restrict__ x,
                             const float* __restrict__ gamma,
                             const float* __restrict__ beta,
                             float* __restrict__ out) {
    int i = blockIdx.x * blockDim.x + threadIdx.x;
    if (i < NPTS*DD) {
        int d = i & 63;
        float yv = (g_y[i] - g_mv[d]) * g_mv[64 + d] * gamma[d] + beta[d];
        out[i] = fmaxf(yv, 0.0f) + x[i];
    }
}

// ---------------- launch -----------------------------------------------------
extern "C" void kernel_launch(void* const* d_in, const int* in_sizes, int n_in,
                              void* d_out, int out_size) {
    const float* x     = (const float*)d_in[0];
    const float* pos   = (const float*)d_in[1];
    const float* w_qkv = (const float*)d_in[2];
    const float* b_qkv = (const float*)d_in[3];
    const float* w_p1  = (const float*)d_in[4];
    const float* b_p1  = (const float*)d_in[5];
    const float* w_p2  = (const float*)d_in[6];
    const float* b_p2  = (const float*)d_in[7];
    const float* w_a1  = (const float*)d_in[8];
    const float* b_a1  = (const float*)d_in[9];
    const float* w_a2  = (const float*)d_in[10];
    const float* b_a2  = (const float*)d_in[11];
    const float* w_fc  = (const float*)d_in[12];
    const float* b_fc  = (const float*)d_in[13];
    const float* gamma = (const float*)d_in[14];
    const float* beta  = (const float*)d_in[15];
    float* out = (float*)d_out;

    const int smem_qkv  = (64*192 + 64*64) * 4;                  // 64 KB
    const int smem_knn  = (3*NN + 8*512) * 4 + (8*512) * 4;      // 80 KB
    const int smem_attn = 50244 * 4;                             // ~196 KB

    cudaFuncSetAttribute(qkv_kernel,  cudaFuncAttributeMaxDynamicSharedMemorySize, smem_qkv);
    cudaFuncSetAttribute(knn_kernel,  cudaFuncAttributeMaxDynamicSharedMemorySize, smem_knn);
    cudaFuncSetAttribute(attn_kernel, cudaFuncAttributeMaxDynamicSharedMemorySize, smem_attn);

    qkv_kernel<<<NPTS/64, 192, smem_qkv>>>(x, w_qkv, b_qkv);
    knn_kernel<<<NPTS/8, 256, smem_knn>>>(pos);
    attn_kernel<<<GRID3, 256, smem_attn>>>(pos, w_p1, b_p1, w_p2, b_p2,
                                           w_a1, b_a1, w_a2, b_a2, w_fc, b_fc);
    bnstats_kernel<<<1, 64>>>();
    final_kernel<<<(NPTS*DD + 255)/256, 256>>>(x, gamma, beta, out);
}

// round 2
// speedup vs baseline: 1.1482x; 1.1482x over previous
#include <cuda_runtime.h>
#include <math.h>

#define BB 2
#define NN 4096
#define DD 64
#define HH 256
#define KK 16
#define NPTS (BB*NN)
#define GRID3 148
#define ROWS 64            // 4 points * 16 neighbors per iteration
#define RP 65              // padded row stride

// ---------------- scratch ----------------------------------------------------
__device__ float g_qkv[NPTS*192];      // q|k|v per point
__device__ int   g_idx[NPTS*KK];       // knn indices
__device__ float g_y[NPTS*DD];         // pre-BN output of fc
__device__ float g_part[GRID3*2*DD];   // per-block partial sum / sumsq
__device__ float g_mv[2*DD];           // mean, rstd

// ---------------- kernel 1: QKV GEMM  (8192x64 @ 64x192) -------------------
__global__ void qkv_kernel(const float* __restrict__ x,
                           const float* __restrict__ w,
                           const float* __restrict__ bq) {
    extern __shared__ float sm[];
    float* ws = sm;             // 64*192
    float* xs = sm + 64*192;    // 64*64
    int tid = threadIdx.x;      // 192 threads
    for (int i = tid; i < 64*192; i += 192) ws[i] = w[i];
    int row0 = blockIdx.x * 64;
    for (int i = tid; i < 64*64; i += 192) xs[i] = x[row0*64 + i];
    __syncthreads();
    float bb = bq[tid];
    for (int r0 = 0; r0 < 64; r0 += 8) {
        float acc[8];
#pragma unroll
        for (int r = 0; r < 8; r++) acc[r] = bb;
        for (int i = 0; i < 64; i++) {
            float wv = ws[i*192 + tid];
#pragma unroll
            for (int r = 0; r < 8; r++) acc[r] = fmaf(xs[(r0+r)*64 + i], wv, acc[r]);
        }
#pragma unroll
        for (int r = 0; r < 8; r++) g_qkv[(row0 + r0 + r)*192 + tid] = acc[r];
    }
}

// ---------------- kernel 2: exact KNN (top-16 smallest (dist, idx)) --------
__device__ __forceinline__ bool lexless(float d1, int i1, float d2, int i2) {
    return (d1 < d2) || (d1 == d2 && i1 < i2);
}

__global__ void knn_kernel(const float* __restrict__ pos) {
    extern __shared__ float sm[];
    float* posX = sm;                 // NN
    float* posY = posX + NN;          // NN
    float* posZ = posY + NN;          // NN
    float* md   = posZ + NN;          // 8*512
    int*   mi   = (int*)(md + 8*512); // 8*512
    int tid = threadIdx.x;
    int warp = tid >> 5, lane = tid & 31;
    int b = blockIdx.x / (NN/8);
    int n = (blockIdx.x % (NN/8))*8 + warp;
    const float* posB = pos + (size_t)b*NN*3;
    for (int i = tid; i < NN; i += 256) {
        posX[i] = posB[i*3+0];
        posY[i] = posB[i*3+1];
        posZ[i] = posB[i*3+2];
    }
    __syncthreads();
    float px = posX[n], py = posY[n], pz = posZ[n];

    float bd[16]; int bi[16];
#pragma unroll
    for (int j = 0; j < 16; j++) { bd[j] = 3.0e38f; bi[j] = 0x7fff0000 + j; }
    float wd = 3.0e38f; int wi = 0x7fff000F;

    for (int c = lane; c < NN; c += 32) {
        float dx = px - posX[c];
        float dy = py - posY[c];
        float dz = pz - posZ[c];
        float d2 = __fadd_rn(__fadd_rn(__fmul_rn(dx,dx), __fmul_rn(dy,dy)),
                             __fmul_rn(dz,dz));
        float thr2 = __fmul_rn(__fmul_rn(wd, wd), 1.0000005f);
        if (d2 <= thr2) {
            float d = sqrtf(d2);
            if (lexless(d, c, wd, wi)) {
#pragma unroll
                for (int j = 0; j < 16; j++)
                    if (bd[j] == wd && bi[j] == wi) { bd[j] = d; bi[j] = c; }
                wd = bd[0]; wi = bi[0];
#pragma unroll
                for (int j = 1; j < 16; j++)
                    if (lexless(wd, wi, bd[j], bi[j])) { wd = bd[j]; wi = bi[j]; }
            }
        }
    }
    float* mdw = md + warp*512;
    int*   miw = mi + warp*512;
#pragma unroll
    for (int j = 0; j < 16; j++) { mdw[j*32 + lane] = bd[j]; miw[j*32 + lane] = bi[j]; }
    __syncwarp();
    int outbase = (b*NN + n)*KK;
    for (int r = 0; r < 16; r++) {
        float cd = 3.0e38f; int ci = 0x7fffffff; int cpos = 0;
#pragma unroll
        for (int j = 0; j < 16; j++) {
            float dv = mdw[j*32 + lane]; int iv = miw[j*32 + lane];
            if (lexless(dv, iv, cd, ci)) { cd = dv; ci = iv; cpos = j*32 + lane; }
        }
#pragma unroll
        for (int off = 16; off > 0; off >>= 1) {
            float od = __shfl_down_sync(0xffffffffu, cd, off);
            int   oi = __shfl_down_sync(0xffffffffu, ci, off);
            int   op = __shfl_down_sync(0xffffffffu, cpos, off);
            if (lexless(od, oi, cd, ci)) { cd = od; ci = oi; cpos = op; }
        }
        if (lane == 0) { g_idx[outbase + r] = ci; mdw[cpos] = 3.0e38f; }
        __syncwarp();
    }
}

// ---------------- kernel 3: fused gather + MLPs + softmax + fc -------------
// 4 points per iteration => 64 GEMM rows; 4x4 register tiles everywhere.
__global__ __launch_bounds__(256, 1)
void attn_kernel(const float* __restrict__ pos,
                 const float* __restrict__ w_p1, const float* __restrict__ b_p1,
                 const float* __restrict__ w_p2, const float* __restrict__ b_p2,
                 const float* __restrict__ w_a1, const float* __restrict__ b_a1,
                 const float* __restrict__ w_a2, const float* __restrict__ b_a2,
                 const float* __restrict__ w_fc, const float* __restrict__ b_fc) {
    extern __shared__ float sm[];
    float* w_a1s = sm;                 // 16384 [d][j]
    float* w_a2s = w_a1s + 16384;      // 16384 [j][d]
    float* w_p2s = w_a2s + 16384;      // 4096  [p][d]
    float* w_fcs = w_p2s + 4096;       // 4096  [c][d]
    float* w_p1s = w_fcs + 4096;       // 192   [c][p]
    float* b_p1s = w_p1s + 192;        // 64
    float* b_p2s = b_p1s + 64;         // 64
    float* b_a1s = b_p2s + 64;         // 256
    float* b_a2s = b_a1s + 256;        // 64
    float* b_fcs = b_a2s + 64;         // 64
    float* qs    = b_fcs + 64;         // 256  (4 x 64)
    float* p0s   = qs + 256;           // 16   (4 x 4)
    float* rel   = p0s + 16;           // 192  (64 x 3)
    float* aggs  = rel + 192;          // 256
    float* red   = aggs + 256;         // 512
    float* h     = red + 512;          // 64*65
    float* vv    = h + ROWS*RP;        // 64*64
    float* tmp   = vv + ROWS*64;       // 64*65   (t1 -> s1 chunk -> scores)
    int*   sidx  = (int*)(tmp + ROWS*RP); // 64

    int tid = threadIdx.x;
    for (int i = tid; i < 16384; i += 256) w_a1s[i] = w_a1[i];
    for (int i = tid; i < 16384; i += 256) w_a2s[i] = w_a2[i];
    for (int i = tid; i < 4096;  i += 256) w_p2s[i] = w_p2[i];
    for (int i = tid; i < 4096;  i += 256) w_fcs[i] = w_fc[i];
    if (tid < 192) w_p1s[tid] = w_p1[tid];
    b_a1s[tid] = b_a1[tid];
    if (tid < 64) {
        b_p1s[tid] = b_p1[tid]; b_p2s[tid] = b_p2[tid];
        b_a2s[tid] = b_a2[tid]; b_fcs[tid] = b_fc[tid];
    }
    float accY = 0.0f, accY2 = 0.0f;    // per-thread BN partials (fixed d = tid&63)

    const int rt = tid >> 4;            // 0..15
    const int ct = tid & 15;            // 0..15
    const int r0 = rt * 4;
    const int c0 = ct * 4;
    __syncthreads();

    for (int g = blockIdx.x; g < NPTS/4; g += gridDim.x) {
        int pbase = g * 4;
        // ---- load per-point data
        if (tid < 64) sidx[tid] = g_idx[pbase*KK + tid];
        {
            int l = tid >> 6, d = tid & 63;
            qs[tid] = g_qkv[(size_t)(pbase + l)*192 + d];
        }
        if (tid < 12) {
            int l = tid / 3, c = tid - l*3;
            p0s[l*4 + c] = pos[(size_t)(pbase + l)*3 + c];
        }
        __syncthreads();

        // ---- gather: h = q - k_nb   (row-major [r][d], pad), vv = v_nb
#pragma unroll
        for (int e = 0; e < 16; e++) {
            int i = tid + e*256;
            int r = i >> 6, d = i & 63;
            int l = r >> 4;
            int bofs = ((pbase + l) >> 12) << 12;
            const float* rowp = g_qkv + (size_t)(bofs + sidx[r])*192;
            h[r*RP + d]  = qs[l*64 + d] - rowp[64 + d];
            vv[r*64 + d] = rowp[128 + d];
        }
        if (tid < 192) {
            int r = tid / 3, c = tid - r*3;
            int l = r >> 4;
            int bofs = ((pbase + l) >> 12) << 12;
            rel[tid] = p0s[l*4 + c] - pos[(size_t)(bofs + sidx[r])*3 + c];
        }
        __syncthreads();

        // ---- pos-MLP hidden: t1 = relu(rel @ w_p1 + b_p1) -> tmp[r][p]
#pragma unroll
        for (int e = 0; e < 16; e++) {
            int i = tid + e*256;
            int r = i >> 6, pp = i & 63;
            float a = b_p1s[pp];
            a = fmaf(rel[r*3+0], w_p1s[pp],        a);
            a = fmaf(rel[r*3+1], w_p1s[64 + pp],   a);
            a = fmaf(rel[r*3+2], w_p1s[128 + pp],  a);
            tmp[r*RP + pp] = fmaxf(a, 0.0f);
        }
        __syncthreads();

        // ---- h += t1 @ w_p2 + b_p2    (4r x 4d tiles)
        {
            float acc[16];
#pragma unroll
            for (int z = 0; z < 16; z++) acc[z] = 0.0f;
            for (int p_ = 0; p_ < 64; p_++) {
                float4 w = *(const float4*)&w_p2s[p_*64 + c0];
                float a0 = tmp[(r0+0)*RP + p_];
                float a1 = tmp[(r0+1)*RP + p_];
                float a2 = tmp[(r0+2)*RP + p_];
                float a3 = tmp[(r0+3)*RP + p_];
                acc[0]  = fmaf(a0, w.x, acc[0]);  acc[1]  = fmaf(a0, w.y, acc[1]);
                acc[2]  = fmaf(a0, w.z, acc[2]);  acc[3]  = fmaf(a0, w.w, acc[3]);
                acc[4]  = fmaf(a1, w.x, acc[4]);  acc[5]  = fmaf(a1, w.y, acc[5]);
                acc[6]  = fmaf(a1, w.z, acc[6]);  acc[7]  = fmaf(a1, w.w, acc[7]);
                acc[8]  = fmaf(a2, w.x, acc[8]);  acc[9]  = fmaf(a2, w.y, acc[9]);
                acc[10] = fmaf(a2, w.z, acc[10]); acc[11] = fmaf(a2, w.w, acc[11]);
                acc[12] = fmaf(a3, w.x, acc[12]); acc[13] = fmaf(a3, w.y, acc[13]);
                acc[14] = fmaf(a3, w.z, acc[14]); acc[15] = fmaf(a3, w.w, acc[15]);
            }
#pragma unroll
            for (int i = 0; i < 4; i++)
#pragma unroll
                for (int j = 0; j < 4; j++)
                    h[(r0+i)*RP + c0 + j] += acc[i*4+j] + b_p2s[c0 + j];
        }
        __syncthreads();

        // ---- fused attn MLP: 4 chunks of 64 hidden cols
        float sacc[16];
#pragma unroll
        for (int z = 0; z < 16; z++) sacc[z] = 0.0f;

        for (int jc = 0; jc < 4; jc++) {
            // phase a: s1c = relu(h @ w_a1[:, jc*64 + (0..63)] + b) -> tmp[r][j]
            float acc[16];
#pragma unroll
            for (int z = 0; z < 16; z++) acc[z] = 0.0f;
            for (int d = 0; d < 64; d++) {
                float4 w = *(const float4*)&w_a1s[d*256 + jc*64 + c0];
                float h0 = h[(r0+0)*RP + d];
                float h1 = h[(r0+1)*RP + d];
                float h2 = h[(r0+2)*RP + d];
                float h3 = h[(r0+3)*RP + d];
                acc[0]  = fmaf(h0, w.x, acc[0]);  acc[1]  = fmaf(h0, w.y, acc[1]);
                acc[2]  = fmaf(h0, w.z, acc[2]);  acc[3]  = fmaf(h0, w.w, acc[3]);
                acc[4]  = fmaf(h1, w.x, acc[4]);  acc[5]  = fmaf(h1, w.y, acc[5]);
                acc[6]  = fmaf(h1, w.z, acc[6]);  acc[7]  = fmaf(h1, w.w, acc[7]);
                acc[8]  = fmaf(h2, w.x, acc[8]);  acc[9]  = fmaf(h2, w.y, acc[9]);
                acc[10] = fmaf(h2, w.z, acc[10]); acc[11] = fmaf(h2, w.w, acc[11]);
                acc[12] = fmaf(h3, w.x, acc[12]); acc[13] = fmaf(h3, w.y, acc[13]);
                acc[14] = fmaf(h3, w.z, acc[14]); acc[15] = fmaf(h3, w.w, acc[15]);
            }
#pragma unroll
            for (int i = 0; i < 4; i++)
#pragma unroll
                for (int j = 0; j < 4; j++)
                    tmp[(r0+i)*RP + c0 + j] =
                        fmaxf(acc[i*4+j] + b_a1s[jc*64 + c0 + j], 0.0f);
            __syncthreads();

            // phase b: sacc += s1c @ w_a2[jc*64 + j][d]
            for (int j = 0; j < 64; j++) {
                float4 w = *(const float4*)&w_a2s[(jc*64 + j)*64 + c0];
                float s0 = tmp[(r0+0)*RP + j];
                float s1v = tmp[(r0+1)*RP + j];
                float s2 = tmp[(r0+2)*RP + j];
                float s3 = tmp[(r0+3)*RP + j];
                sacc[0]  = fmaf(s0, w.x, sacc[0]);  sacc[1]  = fmaf(s0, w.y, sacc[1]);
                sacc[2]  = fmaf(s0, w.z, sacc[2]);  sacc[3]  = fmaf(s0, w.w, sacc[3]);
                sacc[4]  = fmaf(s1v, w.x, sacc[4]); sacc[5]  = fmaf(s1v, w.y, sacc[5]);
                sacc[6]  = fmaf(s1v, w.z, sacc[6]); sacc[7]  = fmaf(s1v, w.w, sacc[7]);
                sacc[8]  = fmaf(s2, w.x, sacc[8]);  sacc[9]  = fmaf(s2, w.y, sacc[9]);
                sacc[10] = fmaf(s2, w.z, sacc[10]); sacc[11] = fmaf(s2, w.w, sacc[11]);
                sacc[12] = fmaf(s3, w.x, sacc[12]); sacc[13] = fmaf(s3, w.y, sacc[13]);
                sacc[14] = fmaf(s3, w.z, sacc[14]); sacc[15] = fmaf(s3, w.w, sacc[15]);
            }
            __syncthreads();
        }

        // ---- write scores (+bias) into tmp[r][d]
#pragma unroll
        for (int i = 0; i < 4; i++)
#pragma unroll
            for (int j = 0; j < 4; j++)
                tmp[(r0+i)*RP + c0 + j] = sacc[i*4+j] + b_a2s[c0 + j];
        __syncthreads();

        // ---- softmax over K per (point, channel) + weighted v-sum
        {
            int l = tid >> 6, d = tid & 63;
            float mx = -3.0e38f;
#pragma unroll
            for (int k = 0; k < 16; k++)
                mx = fmaxf(mx, tmp[(l*16 + k)*RP + d]);
            float s = 0.0f, a = 0.0f;
#pragma unroll
            for (int k = 0; k < 16; k++) {
                float e = expf(tmp[(l*16 + k)*RP + d] - mx);
                s += e;
                a = fmaf(e, vv[(l*16 + k)*64 + d], a);
            }
            aggs[tid] = a / s;
        }
        __syncthreads();

        // ---- fc + BN partials (registers)
        {
            int l = tid >> 6, d = tid & 63;
            float y = b_fcs[d];
            for (int c = 0; c < 64; c++)
                y = fmaf(aggs[l*64 + c], w_fcs[c*64 + d], y);
            g_y[(size_t)(pbase + l)*64 + d] = y;
            accY += y;
            accY2 = fmaf(y, y, accY2);
        }
        __syncthreads();
    }

    // ---- reduce BN partials across the 4 l-groups
    red[tid] = accY;
    __syncthreads();
    if (tid < 64) {
        g_part[blockIdx.x*128 + tid] =
            red[tid] + red[64 + tid] + red[128 + tid] + red[192 + tid];
    }
    __syncthreads();
    red[tid] = accY2;
    __syncthreads();
    if (tid < 64) {
        g_part[blockIdx.x*128 + 64 + tid] =
            red[tid] + red[64 + tid] + red[128 + tid] + red[192 + tid];
    }
}

// ---------------- kernel 4: finish BN statistics ----------------------------
__global__ void bnstats_kernel() {
    __shared__ float sred[512];
    int tid = threadIdx.x;            // 256
    int d = tid & 63, q = tid >> 6;
    float s = 0.0f, s2 = 0.0f;
    for (int blk = q; blk < GRID3; blk += 4) {
        s  += g_part[blk*128 + d];
        s2 += g_part[blk*128 + 64 + d];
    }
    sred[tid] = s; sred[256 + tid] = s2;
    __syncthreads();
    if (tid < 64) {
        float ts  = sred[d] + sred[64+d] + sred[128+d] + sred[192+d];
        float ts2 = sred[256+d] + sred[320+d] + sred[384+d] + sred[448+d];
        float mean = ts / (float)NPTS;
        float var  = ts2 / (float)NPTS - mean*mean;
        g_mv[d]      = mean;
        g_mv[64 + d] = rsqrtf(var + 1e-5f);
    }
}

// ---------------- kernel 5: BN apply + relu + residual ----------------------
__global__ void final_kernel(const float* __restrict__ x,
                             const float* __restrict__ gamma,
                             const float* __restrict__ beta,
                             float* __restrict__ out) {
    int i = blockIdx.x * blockDim.x + threadIdx.x;
    if (i < NPTS*DD) {
        int d = i & 63;
        float yv = (g_y[i] - g_mv[d]) * g_mv[64 + d] * gamma[d] + beta[d];
        out[i] = fmaxf(yv, 0.0f) + x[i];
    }
}

// ---------------- launch -----------------------------------------------------
extern "C" void kernel_launch(void* const* d_in, const int* in_sizes, int n_in,
                              void* d_out, int out_size) {
    const float* x     = (const float*)d_in[0];
    const float* pos   = (const float*)d_in[1];
    const float* w_qkv = (const float*)d_in[2];
    const float* b_qkv = (const float*)d_in[3];
    const float* w_p1  = (const float*)d_in[4];
    const float* b_p1  = (const float*)d_in[5];
    const float* w_p2  = (const float*)d_in[6];
    const float* b_p2  = (const float*)d_in[7];
    const float* w_a1  = (const float*)d_in[8];
    const float* b_a1  = (const float*)d_in[9];
    const float* w_a2  = (const float*)d_in[10];
    const float* b_a2  = (const float*)d_in[11];
    const float* w_fc  = (const float*)d_in[12];
    const float* b_fc  = (const float*)d_in[13];
    const float* gamma = (const float*)d_in[14];
    const float* beta  = (const float*)d_in[15];
    float* out = (float*)d_out;

    const int smem_qkv  = (64*192 + 64*64) * 4;
    const int smem_knn  = (3*NN + 8*512) * 4 + (8*512) * 4;
    const int smem_attn = (16384+16384+4096+4096+192+64+64+256+64+64
                           +256+16+192+256+512 + ROWS*RP + ROWS*64 + ROWS*RP
                           + 64) * 4;

    cudaFuncSetAttribute(qkv_kernel,  cudaFuncAttributeMaxDynamicSharedMemorySize, smem_qkv);
    cudaFuncSetAttribute(knn_kernel,  cudaFuncAttributeMaxDynamicSharedMemorySize, smem_knn);
    cudaFuncSetAttribute(attn_kernel, cudaFuncAttributeMaxDynamicSharedMemorySize, smem_attn);

    qkv_kernel<<<NPTS/64, 192, smem_qkv>>>(x, w_qkv, b_qkv);
    knn_kernel<<<NPTS/8, 256, smem_knn>>>(pos);
    attn_kernel<<<GRID3, 256, smem_attn>>>(pos, w_p1, b_p1, w_p2, b_p2,
                                           w_a1, b_a1, w_a2, b_a2, w_fc, b_fc);
    bnstats_kernel<<<1, 256>>>();
    final_kernel<<<(NPTS*DD + 255)/256, 256>>>(x, gamma, beta, out);
}